// round 3
// baseline (speedup 1.0000x reference)
#include <cuda_runtime.h>
#include <math.h>

#define BB 64
#define NN 8192
#define WW 64
#define HH 4
#define CTRL 792   // H*(3W+6)

// ---------------- scratch (no allocation allowed) ----------------
__device__ float g_keys [BB*HH*WW];   // tanh(keys)
__device__ float g_erase[BB*HH*WW];   // sigmoid(erase)
__device__ float g_wvec [BB*HH*WW];   // tanh(write)
__device__ float g_params[BB*HH*8];   // beta,gate,s0,s1,s2,gamma,keynorm
__device__ float g_scores[(size_t)BB*HH*NN];  // beta * cosine
__device__ float g_w     [(size_t)BB*HH*NN];  // final write distribution

__device__ __forceinline__ float softplusf(float x){
    return x > 20.f ? x : log1pf(expf(x));
}
__device__ __forceinline__ float sigmoidf(float x){
    return 1.f/(1.f + expf(-x));
}

// ---------------- k0: control transforms (tiny) ----------------
__global__ void k0_controls(const float* __restrict__ ctrl){
    int bh = blockIdx.x;                 // b*4+h
    int b  = bh >> 2, h = bh & 3;
    int t  = threadIdx.x;                // 64 threads
    const float* c = ctrl + b*CTRL;

    float k = tanhf(c[h*WW + t]);
    g_keys [bh*WW + t] = k;
    g_erase[bh*WW + t] = sigmoidf(c[256 + h*WW + t]);
    g_wvec [bh*WW + t] = tanhf(c[512 + h*WW + t]);

    __shared__ float s2[2];
    float sq = k*k;
    #pragma unroll
    for (int o = 16; o; o >>= 1) sq += __shfl_xor_sync(0xffffffffu, sq, o);
    if ((t & 31) == 0) s2[t >> 5] = sq;
    __syncthreads();
    if (t == 0){
        float nrm   = sqrtf(s2[0] + s2[1]);
        float beta  = softplusf(c[768 + h]);
        float gate  = sigmoidf(c[772 + h]);
        float gamma = 1.f + softplusf(c[788 + h]);
        float a0 = c[776 + h*3 + 0], a1 = c[776 + h*3 + 1], a2 = c[776 + h*3 + 2];
        float m  = fmaxf(a0, fmaxf(a1, a2));
        float e0 = expf(a0 - m), e1 = expf(a1 - m), e2 = expf(a2 - m);
        float inv = 1.f/(e0 + e1 + e2);
        float* p = g_params + bh*8;
        p[0]=beta; p[1]=gate; p[2]=e0*inv; p[3]=e1*inv; p[4]=e2*inv; p[5]=gamma; p[6]=nrm;
    }
}

// ---------------- k1: beta * cosine scores (streams memory once) ----------------
#define K1_ROWS 64
__global__ __launch_bounds__(256) void k1_scores(const float* __restrict__ mem){
    int b  = blockIdx.y;
    int n0 = blockIdx.x * K1_ROWS;
    __shared__ float skey[HH][WW];
    __shared__ float sb[HH], skn[HH];
    int t = threadIdx.x;
    skey[t >> 6][t & 63] = g_keys[b*HH*WW + t];
    if (t < HH){ sb[t] = g_params[(b*HH + t)*8 + 0]; skn[t] = g_params[(b*HH + t)*8 + 6]; }
    __syncthreads();

    int lane = t & 15, r = t >> 4;
    float4 k0v = ((const float4*)skey[0])[lane];
    float4 k1v = ((const float4*)skey[1])[lane];
    float4 k2v = ((const float4*)skey[2])[lane];
    float4 k3v = ((const float4*)skey[3])[lane];

    #pragma unroll
    for (int i = 0; i < K1_ROWS/16; i++){
        int n = n0 + r + 16*i;
        float4 m = ((const float4*)mem)[((size_t)b*NN + n)*16 + lane];
        float sq = m.x*m.x + m.y*m.y + m.z*m.z + m.w*m.w;
        float d0 = m.x*k0v.x + m.y*k0v.y + m.z*k0v.z + m.w*k0v.w;
        float d1 = m.x*k1v.x + m.y*k1v.y + m.z*k1v.z + m.w*k1v.w;
        float d2 = m.x*k2v.x + m.y*k2v.y + m.z*k2v.z + m.w*k2v.w;
        float d3 = m.x*k3v.x + m.y*k3v.y + m.z*k3v.z + m.w*k3v.w;
        #pragma unroll
        for (int o = 8; o; o >>= 1){
            sq += __shfl_xor_sync(0xffffffffu, sq, o);
            d0 += __shfl_xor_sync(0xffffffffu, d0, o);
            d1 += __shfl_xor_sync(0xffffffffu, d1, o);
            d2 += __shfl_xor_sync(0xffffffffu, d2, o);
            d3 += __shfl_xor_sync(0xffffffffu, d3, o);
        }
        if (lane == 0){
            float mn = sqrtf(sq);
            size_t base = (size_t)b*HH*NN + n;
            g_scores[base + 0*(size_t)NN] = sb[0]*d0/(skn[0]*mn + 1e-8f);
            g_scores[base + 1*(size_t)NN] = sb[1]*d1/(skn[1]*mn + 1e-8f);
            g_scores[base + 2*(size_t)NN] = sb[2]*d2/(skn[2]*mn + 1e-8f);
            g_scores[base + 3*(size_t)NN] = sb[3]*d3/(skn[3]*mn + 1e-8f);
        }
    }
}

// ---------------- k2: softmax + interp + shift + sharpen, one block per (b,h) ----
__device__ __forceinline__ float blk_reduce(float v, bool is_max, float* red, float* bc){
    int t = threadIdx.x, lane = t & 31, wid = t >> 5;
    #pragma unroll
    for (int o = 16; o; o >>= 1){
        float u = __shfl_xor_sync(0xffffffffu, v, o);
        v = is_max ? fmaxf(v, u) : (v + u);
    }
    __syncthreads();                 // protect red/bc from previous use
    if (lane == 0) red[wid] = v;
    __syncthreads();
    if (t == 0){
        float a = red[0];
        #pragma unroll
        for (int k = 1; k < 8; k++) a = is_max ? fmaxf(a, red[k]) : (a + red[k]);
        *bc = a;
    }
    __syncthreads();
    return *bc;
}

__global__ __launch_bounds__(256) void k2_weights(const float* __restrict__ prev){
    int bh = blockIdx.x;
    __shared__ float sm[NN];
    __shared__ float red[8];
    __shared__ float bc;
    int t = threadIdx.x;

    const float* p = g_params + bh*8;
    float gate = p[1], s0 = p[2], s1 = p[3], s2 = p[4], gamma = p[5];

    const float* sc = g_scores + (size_t)bh*NN;
    float lmax = -1e30f;
    #pragma unroll
    for (int j = 0; j < 32; j++){
        int n = t + 256*j;
        float s = sc[n];
        sm[n] = s;
        lmax = fmaxf(lmax, s);
    }
    float M = blk_reduce(lmax, true, red, &bc);

    float lsum = 0.f;
    #pragma unroll
    for (int j = 0; j < 32; j++){
        int n = t + 256*j;
        float e = expf(sm[n] - M);
        sm[n] = e;
        lsum += e;
    }
    float S = blk_reduce(lsum, false, red, &bc);
    float invS = 1.f / S;

    const float* pr = prev + (size_t)bh*NN;
    #pragma unroll
    for (int j = 0; j < 32; j++){
        int n = t + 256*j;
        sm[n] = gate * (sm[n] * invS) + (1.f - gate) * pr[n];
    }
    __syncthreads();                 // all w_interp visible before shift

    float v[32];
    float ls = 0.f;
    #pragma unroll
    for (int j = 0; j < 32; j++){
        int n  = t + 256*j;
        int nm = (n + NN - 1) & (NN - 1);
        int np = (n + 1) & (NN - 1);
        float x = s0*sm[nm] + s1*sm[n] + s2*sm[np];
        float pw = powf(x, gamma);
        v[j] = pw;
        ls += pw;
    }
    float T = blk_reduce(ls, false, red, &bc);
    float invT = 1.f / (T + 1e-8f);

    float* wout = g_w + (size_t)bh*NN;
    #pragma unroll
    for (int j = 0; j < 32; j++) wout[t + 256*j] = v[j] * invT;
}

// ---------------- k3: erase/add update (streams memory + output) ----------------
#define K3_ROWS 64
__global__ __launch_bounds__(256) void k3_out(const float* __restrict__ mem,
                                             float* __restrict__ out){
    int b  = blockIdx.y;
    int n0 = blockIdx.x * K3_ROWS;
    __shared__ float se[HH][WW], sv[HH][WW];
    int t = threadIdx.x;
    se[t >> 6][t & 63] = g_erase[b*HH*WW + t];
    sv[t >> 6][t & 63] = g_wvec [b*HH*WW + t];
    __syncthreads();

    int lane = t & 15, r = t >> 4;
    float4 e0 = ((const float4*)se[0])[lane];
    float4 e1 = ((const float4*)se[1])[lane];
    float4 e2 = ((const float4*)se[2])[lane];
    float4 e3 = ((const float4*)se[3])[lane];
    float4 w0 = ((const float4*)sv[0])[lane];
    float4 w1 = ((const float4*)sv[1])[lane];
    float4 w2 = ((const float4*)sv[2])[lane];
    float4 w3 = ((const float4*)sv[3])[lane];

    const float* wp = g_w + (size_t)b*HH*NN;

    #pragma unroll
    for (int i = 0; i < K3_ROWS/16; i++){
        int n = n0 + r + 16*i;
        float a0 = __ldg(wp + n);
        float a1 = __ldg(wp + (size_t)NN   + n);
        float a2 = __ldg(wp + (size_t)2*NN + n);
        float a3 = __ldg(wp + (size_t)3*NN + n);
        size_t idx = ((size_t)b*NN + n)*16 + lane;
        float4 m = ((const float4*)mem)[idx];
        float4 o;
        o.x = m.x*(1.f-a0*e0.x)*(1.f-a1*e1.x)*(1.f-a2*e2.x)*(1.f-a3*e3.x)
            + a0*w0.x + a1*w1.x + a2*w2.x + a3*w3.x;
        o.y = m.y*(1.f-a0*e0.y)*(1.f-a1*e1.y)*(1.f-a2*e2.y)*(1.f-a3*e3.y)
            + a0*w0.y + a1*w1.y + a2*w2.y + a3*w3.y;
        o.z = m.z*(1.f-a0*e0.z)*(1.f-a1*e1.z)*(1.f-a2*e2.z)*(1.f-a3*e3.z)
            + a0*w0.z + a1*w1.z + a2*w2.z + a3*w3.z;
        o.w = m.w*(1.f-a0*e0.w)*(1.f-a1*e1.w)*(1.f-a2*e2.w)*(1.f-a3*e3.w)
            + a0*w0.w + a1*w1.w + a2*w2.w + a3*w3.w;
        ((float4*)out)[idx] = o;
    }
}

// ---------------- launch ----------------
extern "C" void kernel_launch(void* const* d_in, const int* in_sizes, int n_in,
                              void* d_out, int out_size) {
    const float* mem  = (const float*)d_in[0];   // [B,N,W]
    const float* ctrl = (const float*)d_in[1];   // [B,792]
    const float* prev = (const float*)d_in[2];   // [B,H,N]
    float* out = (float*)d_out;                  // [B,N,W]

    k0_controls<<<BB*HH, 64>>>(ctrl);
    k1_scores  <<<dim3(NN/K1_ROWS, BB), 256>>>(mem);
    k2_weights <<<BB*HH, 256>>>(prev);
    k3_out     <<<dim3(NN/K3_ROWS, BB), 256>>>(mem, out);
    (void)in_sizes; (void)n_in; (void)out_size;
}

// round 5
// speedup vs baseline: 1.2032x; 1.2032x over previous
#include <cuda_runtime.h>
#include <math.h>

#define BB 64
#define NN 8192
#define WW 64
#define HH 4
#define CTRL 792   // H*(3W+6)

// ---------------- scratch (no allocation allowed) ----------------
__device__ float g_keys [BB*HH*WW];   // tanh(keys)
__device__ float g_erase[BB*HH*WW];   // sigmoid(erase)
__device__ float g_wvec [BB*HH*WW];   // tanh(write)
__device__ float g_params[BB*HH*8];   // beta,gate,s0,s1,s2,gamma,keynorm
__device__ float g_scores[(size_t)BB*HH*NN];  // beta * cosine
__device__ float g_w     [(size_t)BB*HH*NN];  // final write distribution

__device__ __forceinline__ float softplusf(float x){
    return x > 20.f ? x : log1pf(expf(x));
}
__device__ __forceinline__ float sigmoidf(float x){
    return 1.f/(1.f + expf(-x));
}

// ---------------- k0: control transforms (tiny) ----------------
__global__ void k0_controls(const float* __restrict__ ctrl){
    int bh = blockIdx.x;                 // b*4+h
    int b  = bh >> 2, h = bh & 3;
    int t  = threadIdx.x;                // 64 threads
    const float* c = ctrl + b*CTRL;

    float k = tanhf(c[h*WW + t]);
    g_keys [bh*WW + t] = k;
    g_erase[bh*WW + t] = sigmoidf(c[256 + h*WW + t]);
    g_wvec [bh*WW + t] = tanhf(c[512 + h*WW + t]);

    __shared__ float s2[2];
    float sq = k*k;
    #pragma unroll
    for (int o = 16; o; o >>= 1) sq += __shfl_xor_sync(0xffffffffu, sq, o);
    if ((t & 31) == 0) s2[t >> 5] = sq;
    __syncthreads();
    if (t == 0){
        float nrm   = sqrtf(s2[0] + s2[1]);
        float beta  = softplusf(c[768 + h]);
        float gate  = sigmoidf(c[772 + h]);
        float gamma = 1.f + softplusf(c[788 + h]);
        float a0 = c[776 + h*3 + 0], a1 = c[776 + h*3 + 1], a2 = c[776 + h*3 + 2];
        float m  = fmaxf(a0, fmaxf(a1, a2));
        float e0 = expf(a0 - m), e1 = expf(a1 - m), e2 = expf(a2 - m);
        float inv = 1.f/(e0 + e1 + e2);
        float* p = g_params + bh*8;
        p[0]=beta; p[1]=gate; p[2]=e0*inv; p[3]=e1*inv; p[4]=e2*inv; p[5]=gamma; p[6]=nrm;
    }
}

// ---------------- k1: beta * cosine scores -------------------------------
// 4 lanes per memory row, 16 floats (4 float4) per lane.
// Only 2 shuffle rounds to reduce 5 accumulators across the 4-lane group.
#define K1_ROWSPB 64
__global__ __launch_bounds__(256) void k1_scores(const float* __restrict__ mem){
    int b  = blockIdx.y;
    int n0 = blockIdx.x * K1_ROWSPB;
    __shared__ float skey[HH*WW];
    __shared__ float sb[HH], skn[HH];
    int t = threadIdx.x;
    skey[t] = g_keys[b*HH*WW + t];
    if (t < HH){ sb[t] = g_params[(b*HH + t)*8 + 0]; skn[t] = g_params[(b*HH + t)*8 + 6]; }
    __syncthreads();

    int seg = t & 3;            // which 16-float segment of W
    int row = n0 + (t >> 2);    // one memory row per thread

    const float4* mrow = (const float4*)(mem + ((size_t)b*NN + row)*WW) + seg*4;
    float4 m0 = mrow[0], m1 = mrow[1], m2 = mrow[2], m3 = mrow[3];

    float sq = m0.x*m0.x + m0.y*m0.y + m0.z*m0.z + m0.w*m0.w
             + m1.x*m1.x + m1.y*m1.y + m1.z*m1.z + m1.w*m1.w
             + m2.x*m2.x + m2.y*m2.y + m2.z*m2.z + m2.w*m2.w
             + m3.x*m3.x + m3.y*m3.y + m3.z*m3.z + m3.w*m3.w;

    float d[HH];
    #pragma unroll
    for (int h = 0; h < HH; h++){
        const float4* kp = (const float4*)(skey + h*WW) + seg*4;
        float4 k0 = kp[0], k1 = kp[1], k2 = kp[2], k3 = kp[3];
        d[h] = m0.x*k0.x + m0.y*k0.y + m0.z*k0.z + m0.w*k0.w
             + m1.x*k1.x + m1.y*k1.y + m1.z*k1.z + m1.w*k1.w
             + m2.x*k2.x + m2.y*k2.y + m2.z*k2.z + m2.w*k2.w
             + m3.x*k3.x + m3.y*k3.y + m3.z*k3.z + m3.w*k3.w;
    }

    // reduce over the 4-lane group (xor 1, 2)
    #pragma unroll
    for (int o = 1; o <= 2; o <<= 1){
        sq   += __shfl_xor_sync(0xffffffffu, sq,   o);
        d[0] += __shfl_xor_sync(0xffffffffu, d[0], o);
        d[1] += __shfl_xor_sync(0xffffffffu, d[1], o);
        d[2] += __shfl_xor_sync(0xffffffffu, d[2], o);
        d[3] += __shfl_xor_sync(0xffffffffu, d[3], o);
    }

    if (seg == 0){
        float mn = sqrtf(sq);
        size_t base = (size_t)b*HH*NN + row;
        #pragma unroll
        for (int h = 0; h < HH; h++)
            g_scores[base + (size_t)h*NN] = sb[h]*d[h]/(skn[h]*mn + 1e-8f);
    }
}

// ---------------- k2: softmax + interp + shift + sharpen, one block per (b,h) ----
__device__ __forceinline__ float blk_reduce(float v, bool is_max, float* red, float* bc){
    int t = threadIdx.x, lane = t & 31, wid = t >> 5;
    #pragma unroll
    for (int o = 16; o; o >>= 1){
        float u = __shfl_xor_sync(0xffffffffu, v, o);
        v = is_max ? fmaxf(v, u) : (v + u);
    }
    __syncthreads();                 // protect red/bc from previous use
    if (lane == 0) red[wid] = v;
    __syncthreads();
    if (t == 0){
        float a = red[0];
        #pragma unroll
        for (int k = 1; k < 8; k++) a = is_max ? fmaxf(a, red[k]) : (a + red[k]);
        *bc = a;
    }
    __syncthreads();
    return *bc;
}

__global__ __launch_bounds__(256) void k2_weights(const float* __restrict__ prev){
    int bh = blockIdx.x;
    __shared__ float sm[NN];
    __shared__ float red[8];
    __shared__ float bc;
    int t = threadIdx.x;

    const float* p = g_params + bh*8;
    float gate = p[1], s0 = p[2], s1 = p[3], s2 = p[4], gamma = p[5];

    const float* sc = g_scores + (size_t)bh*NN;
    float lmax = -1e30f;
    #pragma unroll
    for (int j = 0; j < 32; j++){
        int n = t + 256*j;
        float s = __ldg(sc + n);
        sm[n] = s;
        lmax = fmaxf(lmax, s);
    }
    float M = blk_reduce(lmax, true, red, &bc);

    float lsum = 0.f;
    #pragma unroll
    for (int j = 0; j < 32; j++){
        int n = t + 256*j;
        float e = __expf(sm[n] - M);
        sm[n] = e;
        lsum += e;
    }
    float S = blk_reduce(lsum, false, red, &bc);
    float invS = 1.f / S;

    const float* pr = prev + (size_t)bh*NN;
    #pragma unroll
    for (int j = 0; j < 32; j++){
        int n = t + 256*j;
        sm[n] = gate * (sm[n] * invS) + (1.f - gate) * __ldg(pr + n);
    }
    __syncthreads();                 // all w_interp visible before shift

    float v[32];
    float ls = 0.f;
    #pragma unroll
    for (int j = 0; j < 32; j++){
        int n  = t + 256*j;
        int nm = (n + NN - 1) & (NN - 1);
        int np = (n + 1) & (NN - 1);
        float x = s0*sm[nm] + s1*sm[n] + s2*sm[np];
        float pw = __powf(x, gamma);
        v[j] = pw;
        ls += pw;
    }
    float T = blk_reduce(ls, false, red, &bc);
    float invT = 1.f / (T + 1e-8f);

    float* wout = g_w + (size_t)bh*NN;
    #pragma unroll
    for (int j = 0; j < 32; j++) wout[t + 256*j] = v[j] * invT;
}

// ---------------- k3: erase/add update (streams memory + output) ----------------
// __launch_bounds__(256,5): cap regs (~51) so 5 CTAs/SM fit -> ~62% occupancy.
#define K3_ROWS 64
__global__ __launch_bounds__(256, 5) void k3_out(const float* __restrict__ mem,
                                                 float* __restrict__ out){
    int b  = blockIdx.y;
    int n0 = blockIdx.x * K3_ROWS;
    __shared__ float se[HH][WW], sv[HH][WW];
    int t = threadIdx.x;
    se[t >> 6][t & 63] = g_erase[b*HH*WW + t];
    sv[t >> 6][t & 63] = g_wvec [b*HH*WW + t];
    __syncthreads();

    int lane = t & 15, r = t >> 4;
    const float* wp = g_w + (size_t)b*HH*NN;

    #pragma unroll
    for (int i = 0; i < K3_ROWS/16; i++){
        int n = n0 + r + 16*i;
        float a0 = __ldg(wp + n);
        float a1 = __ldg(wp + (size_t)NN   + n);
        float a2 = __ldg(wp + (size_t)2*NN + n);
        float a3 = __ldg(wp + (size_t)3*NN + n);
        size_t idx = ((size_t)b*NN + n)*16 + lane;
        float4 m = ((const float4*)mem)[idx];

        float4 e0 = ((const float4*)se[0])[lane];
        float4 e1 = ((const float4*)se[1])[lane];
        float4 e2 = ((const float4*)se[2])[lane];
        float4 e3 = ((const float4*)se[3])[lane];
        float4 w0 = ((const float4*)sv[0])[lane];
        float4 w1 = ((const float4*)sv[1])[lane];
        float4 w2 = ((const float4*)sv[2])[lane];
        float4 w3 = ((const float4*)sv[3])[lane];

        float4 o;
        o.x = m.x*(1.f-a0*e0.x)*(1.f-a1*e1.x)*(1.f-a2*e2.x)*(1.f-a3*e3.x)
            + a0*w0.x + a1*w1.x + a2*w2.x + a3*w3.x;
        o.y = m.y*(1.f-a0*e0.y)*(1.f-a1*e1.y)*(1.f-a2*e2.y)*(1.f-a3*e3.y)
            + a0*w0.y + a1*w1.y + a2*w2.y + a3*w3.y;
        o.z = m.z*(1.f-a0*e0.z)*(1.f-a1*e1.z)*(1.f-a2*e2.z)*(1.f-a3*e3.z)
            + a0*w0.z + a1*w1.z + a2*w2.z + a3*w3.z;
        o.w = m.w*(1.f-a0*e0.w)*(1.f-a1*e1.w)*(1.f-a2*e2.w)*(1.f-a3*e3.w)
            + a0*w0.w + a1*w1.w + a2*w2.w + a3*w3.w;
        ((float4*)out)[idx] = o;
    }
}

// ---------------- launch ----------------
extern "C" void kernel_launch(void* const* d_in, const int* in_sizes, int n_in,
                              void* d_out, int out_size) {
    const float* mem  = (const float*)d_in[0];   // [B,N,W]
    const float* ctrl = (const float*)d_in[1];   // [B,792]
    const float* prev = (const float*)d_in[2];   // [B,H,N]
    float* out = (float*)d_out;                  // [B,N,W]

    k0_controls<<<BB*HH, 64>>>(ctrl);
    k1_scores  <<<dim3(NN/K1_ROWSPB, BB), 256>>>(mem);
    k2_weights <<<BB*HH, 256>>>(prev);
    k3_out     <<<dim3(NN/K3_ROWS, BB), 256>>>(mem, out);
    (void)in_sizes; (void)n_in; (void)out_size;
}